// round 11
// baseline (speedup 1.0000x reference)
#include <cuda_runtime.h>

#define HIDDEN   1024
#define SEQ      784
#define BATCH    512
#define NTHREADS 256
#define NWARPS   (NTHREADS / 32)       // 8
#define SPB      2                     // sequences per block, BOTH carried by EVERY warp
#define E        4                     // hidden states per thread per sequence

// tanh from pre-scaled arg xvK = (2/ln2)*xv:  tanh = 1 - 2/(2^xvK + 1).
// Saturates safely at +-inf (ex2->Inf => rcp->0 => +1 ; ex2->0 => rcp(1)=1 => -1).
__device__ __forceinline__ float tanh_from_scaled(float xvK) {
    float e, rc;
    asm("ex2.approx.ftz.f32 %0, %1;" : "=f"(e) : "f"(xvK));
    asm("rcp.approx.ftz.f32 %0, %1;" : "=f"(rc) : "f"(e + 1.0f));
    return fmaf(-2.0f, rc, 1.0f);
}

// One block serves TWO batch sequences; every warp processes the SAME hidden
// indices for both (constants shared) -> two independent per-step dependency
// DAGs per warp (deterministic intra-warp latency hiding), and ONE barrier +
// ONE ladder pass per pair of sequence-steps. 256 threads restore ~3.5
// warps/SMSP so the SMSP sees ~7 independent chains.
//
// HiPPO bilinear step collapses (A diagonal + rank-1 semiseparable) to ONE
// linear scan over hidden index i:
//   r_{i+1} = alf_i r_i + w_i,  w_i = gam_i h_i + dlt_i u      (r_0 = 0)
//   xv_i    = A1_i h_i + gam_i (c u - (c/2) r_i) ;  h_i = tanh(xv_i)
// Time-invariant multiplicative scan coefficients -> 'a' ladder (saL, eaC,
// cw) precomputed once; per step the warp scan runs on 'b' only.
__global__ void __launch_bounds__(NTHREADS, 2)
ssm_scan_kernel(const float* __restrict__ x,
                const float* __restrict__ C,
                const float* __restrict__ W,
                const float* __restrict__ bias,
                float* __restrict__ out)
{
    __shared__ float  xsv[SEQ * SPB];    // interleaved: xsv[2t+s] = u of seq s at step t
    __shared__ float2 wtb[2][NWARPS];    // warp totals (b) for both seqs, parity-buffered
    __shared__ float  wtot[NWARPS];
    __shared__ float  red[NWARPS][SPB];

    const int tid  = threadIdx.x;
    const int lane = tid & 31;
    const int wid  = tid >> 5;
    const int bidx = blockIdx.x;

    // Stage both sequences, interleaving by step for a single LDS.64 per step.
    for (int i = tid; i < SPB * SEQ; i += NTHREADS) {
        const int s = i / SEQ, t = i - s * SEQ;
        xsv[2 * t + s] = x[(bidx * SPB + s) * SEQ + t];
    }

    const float KT = 2.885390081777927f;          // 2/ln(2)

    // ---- per-element constants, built in double (matches reference fp64 HiPPO);
    //      SHARED between the two sequences (same hidden indices). ----
    float alf[E], gam[E], dlt[E], A1K[E], Ks[E];
    float h0[E], h1[E], w0[E], w1[E];
    float c_f, mc2K;
    {
        const double step = 1.0 / (double)SEQ;
        const double c    = 0.5 * step;
        c_f  = (float)c;
        mc2K = (float)(-0.5 * c) * KT;
        #pragma unroll
        for (int e = 0; e < E; ++e) {
            const double q = (double)(tid * E + e);
            const double P = sqrt(1.0 + 2.0 * q);
            const double D = 1.0 + c * (1.0 + q);
            alf[e] = (float)((1.0 - c * q) / D);
            gam[e] = (float)(2.0 * P / D);
            dlt[e] = (float)(step * P * P / D);
            A1K[e] = (float)((1.0 - c * (1.0 + q)) / D) * KT;
            h0[e] = 0.f; h1[e] = 0.f;
        }
        float p = 1.f;
        #pragma unroll
        for (int e = E - 1; e >= 0; --e) { Ks[e] = p; p *= alf[e]; }
    }

    // ---- one-time 'a' ladder (time-invariant scan coefficients) ----
    float saL[5];
    float sa = Ks[0] * alf[0];
    #pragma unroll
    for (int k = 0; k < 5; ++k) {
        saL[k] = sa;
        float ra = __shfl_up_sync(0xffffffffu, sa, 1 << k);
        if (lane >= (1 << k)) sa *= ra;
    }
    float eaC = __shfl_up_sync(0xffffffffu, sa, 1);
    if (lane == 0) eaC = 1.f;
    if (lane == 31) wtot[wid] = sa;
    __syncthreads();

    // cw[w2] = prod_{w3=w2+1}^{wid-1} wtot[w3] for w2 < wid, else 0.
    float cw[NWARPS - 1];
    {
        float p = 1.f;
        #pragma unroll
        for (int w3 = NWARPS - 2; w3 >= 0; --w3) {
            if (w3 < wid) { cw[w3] = p; p *= wtot[w3]; }
            else           cw[w3] = 0.f;
        }
    }
    __syncthreads();

    // =========================== main time loop ===========================
    #pragma unroll 2
    for (int t = 0; t < SEQ; ++t) {
        const float2 uv  = *(const float2*)&xsv[2 * t];
        const float  u0  = uv.x,                u1  = uv.y;
        const float cuK0 = (c_f * KT) * u0;
        const float cuK1 = (c_f * KT) * u1;

        // ---- thread-local: w_e and cb = sum Ks_e * w_e (both streams) ----
        #pragma unroll
        for (int e = 0; e < E; ++e) {
            w0[e] = fmaf(gam[e], h0[e], dlt[e] * u0);
            w1[e] = fmaf(gam[e], h1[e], dlt[e] * u1);
        }
        float c0a = 0.f, c0b = 0.f, c1a = 0.f, c1b = 0.f;
        #pragma unroll
        for (int e = 0; e < E; e += 2) {
            c0a = fmaf(Ks[e],     w0[e],     c0a);
            c0b = fmaf(Ks[e + 1], w0[e + 1], c0b);
            c1a = fmaf(Ks[e],     w1[e],     c1a);
            c1b = fmaf(Ks[e + 1], w1[e + 1], c1b);
        }
        float sb0 = c0a + c0b;
        float sb1 = c1a + c1b;

        // ---- warp inclusive scan on 'b', two independent streams interleaved ----
        #pragma unroll
        for (int k = 0; k < 5; ++k) {
            float rb0 = __shfl_up_sync(0xffffffffu, sb0, 1 << k);
            float rb1 = __shfl_up_sync(0xffffffffu, sb1, 1 << k);
            if (lane >= (1 << k)) {
                sb0 = fmaf(saL[k], rb0, sb0);
                sb1 = fmaf(saL[k], rb1, sb1);
            }
        }
        float eb0 = __shfl_up_sync(0xffffffffu, sb0, 1);
        float eb1 = __shfl_up_sync(0xffffffffu, sb1, 1);
        if (lane == 0) { eb0 = 0.f; eb1 = 0.f; }

        const int par = t & 1;                       // constant under unroll 2
        if (lane == 31) wtb[par][wid] = make_float2(sb0, sb1);
        __syncthreads();            // ONE barrier advances BOTH sequences one step

        // cross-warp: constant-weighted sums (no chain), one LDS.64 per lower warp
        float gb0 = 0.f, gb1 = 0.f;
        #pragma unroll
        for (int w2 = 0; w2 < NWARPS - 1; ++w2) {
            if (w2 < wid) {
                const float2 v = wtb[par][w2];
                gb0 = fmaf(cw[w2], v.x, gb0);
                gb1 = fmaf(cw[w2], v.y, gb1);
            }
        }
        float r0 = fmaf(eaC, gb0, eb0);
        float r1 = fmaf(eaC, gb1, eb1);

        // ---- apply: two interleaved 1-FMA r-chains; xv/tanh off-chain ----
        #pragma unroll
        for (int e = 0; e < E; ++e) {
            float rho0 = fmaf(mc2K, r0, cuK0);
            float rho1 = fmaf(mc2K, r1, cuK1);
            float xv0  = fmaf(gam[e], rho0, A1K[e] * h0[e]);
            float xv1  = fmaf(gam[e], rho1, A1K[e] * h1[e]);
            r0 = fmaf(alf[e], r0, w0[e]);
            r1 = fmaf(alf[e], r1, w1[e]);
            h0[e] = tanh_from_scaled(xv0);
            h1[e] = tanh_from_scaled(xv1);
        }
    }

    // ---- epilogue: y_s = C . h_s ; out[bidx*2+s][o] = y_s*W[o] + bias[o] ----
    float p0 = 0.f, p1 = 0.f;
    #pragma unroll
    for (int e = 0; e < E; ++e) {
        const float Ce = __ldg(&C[tid * E + e]);
        p0 = fmaf(Ce, h0[e], p0);
        p1 = fmaf(Ce, h1[e], p1);
    }
    #pragma unroll
    for (int d = 16; d > 0; d >>= 1) {
        p0 += __shfl_down_sync(0xffffffffu, p0, d);
        p1 += __shfl_down_sync(0xffffffffu, p1, d);
    }
    if (lane == 0) { red[wid][0] = p0; red[wid][1] = p1; }
    __syncthreads();
    if (tid < SPB) {
        float y = 0.f;
        #pragma unroll
        for (int w2 = 0; w2 < NWARPS; ++w2) y += red[w2][tid];
        #pragma unroll
        for (int o = 0; o < 10; ++o)
            out[(bidx * SPB + tid) * 10 + o] = fmaf(y, W[o], bias[o]);
    }
}

extern "C" void kernel_launch(void* const* d_in, const int* in_sizes, int n_in,
                              void* d_out, int out_size) {
    const float* x    = (const float*)d_in[0];   // (512, 784, 1)
    const float* C    = (const float*)d_in[1];   // (1, 1024)
    const float* W    = (const float*)d_in[2];   // (1, 10)
    const float* bias = (const float*)d_in[3];   // (10,)
    float* out        = (float*)d_out;           // (512, 10)
    ssm_scan_kernel<<<BATCH / SPB, NTHREADS>>>(x, C, W, bias, out);
}

// round 13
// speedup vs baseline: 1.1234x; 1.1234x over previous
#include <cuda_runtime.h>

#define HIDDEN   1024
#define SEQ      784
#define BATCH    512
#define NTHREADS 128
#define NWARPS   4
#define SPB      4                     // sequences per block, ALL carried by EVERY warp
#define E        8                     // hidden states per thread per sequence

// Paired tanh for two pre-scaled args (xvK = (2/ln2)*xv), sharing ONE rcp:
//   tanh = 1 - 2/(E+1);  rc = rcp(D0*D1); 1/D0 = rc*D1; 1/D1 = rc*D0.
// xvK is clamped to <= 30 so D0*D1 <= ~2^60 never overflows (tanh(10.4)
// differs from 1 by 3e-9 -> clamp numerically invisible). Negative xvK is
// safe unclamped (E->0, D->1).
__device__ __forceinline__ void tanh_pair(float xvK0, float xvK1,
                                          float& t0, float& t1) {
    float e0, e1, rc;
    xvK0 = fminf(xvK0, 30.f);
    xvK1 = fminf(xvK1, 30.f);
    asm("ex2.approx.ftz.f32 %0, %1;" : "=f"(e0) : "f"(xvK0));
    asm("ex2.approx.ftz.f32 %0, %1;" : "=f"(e1) : "f"(xvK1));
    const float d0 = e0 + 1.f, d1 = e1 + 1.f;
    asm("rcp.approx.ftz.f32 %0, %1;" : "=f"(rc) : "f"(d0 * d1));
    t0 = fmaf(-2.f, rc * d1, 1.f);
    t1 = fmaf(-2.f, rc * d0, 1.f);
}

// One block serves FOUR batch sequences; every warp processes the SAME hidden
// indices for all four (constants shared) -> four independent per-step
// dependency DAGs per warp (ILP 4 covers FMA latency), and ONE barrier + ONE
// ladder pass per FOUR sequence-steps. grid=128 -> exactly 1 block/SM: no
// cross-block contention, intra-block barrier only.
//
// HiPPO bilinear step collapses (A diagonal + rank-1 semiseparable) to ONE
// linear scan over hidden index i:
//   r_{i+1} = alf_i r_i + w_i,  w_i = gam_i h_i + dlt_i u      (r_0 = 0)
//   xv_i    = A1_i h_i + gam_i (c u - (c/2) r_i) ;  h_i = tanh(xv_i)
// Time-invariant multiplicative scan coefficients -> 'a' ladder (saL, eaC,
// cw) precomputed once; per step the warp scan runs on 'b' only.
__global__ void __launch_bounds__(NTHREADS, 1)
ssm_scan_kernel(const float* __restrict__ x,
                const float* __restrict__ C,
                const float* __restrict__ W,
                const float* __restrict__ bias,
                float* __restrict__ out)
{
    __shared__ float  xsv[SEQ * SPB];    // interleaved: xsv[4t+s] = u of seq s at step t
    __shared__ float4 wtb[2][NWARPS];    // warp totals (b) for 4 seqs, parity-buffered
    __shared__ float  wtot[NWARPS];
    __shared__ float  red[NWARPS][SPB];

    const int tid  = threadIdx.x;
    const int lane = tid & 31;
    const int wid  = tid >> 5;
    const int bidx = blockIdx.x;

    // Stage all four sequences, interleaved by step for one LDS.128 per step.
    for (int i = tid; i < SPB * SEQ; i += NTHREADS) {
        const int s = i / SEQ, t = i - s * SEQ;
        xsv[SPB * t + s] = x[(bidx * SPB + s) * SEQ + t];
    }

    const float KT = 2.885390081777927f;          // 2/ln(2)

    // ---- per-element constants, built in double (matches reference fp64 HiPPO);
    //      SHARED across the four sequences (same hidden indices). ----
    float alf[E], gam[E], dlt[E], A1K[E], Ks[E];
    float h0[E], h1[E], h2[E], h3[E], w0[E], w1[E], w2[E], w3[E];
    float c_f, mc2K;
    {
        const double step = 1.0 / (double)SEQ;
        const double c    = 0.5 * step;
        c_f  = (float)c;
        mc2K = (float)(-0.5 * c) * KT;
        #pragma unroll
        for (int e = 0; e < E; ++e) {
            const double q = (double)(tid * E + e);
            const double P = sqrt(1.0 + 2.0 * q);
            const double D = 1.0 + c * (1.0 + q);
            alf[e] = (float)((1.0 - c * q) / D);
            gam[e] = (float)(2.0 * P / D);
            dlt[e] = (float)(step * P * P / D);
            A1K[e] = (float)((1.0 - c * (1.0 + q)) / D) * KT;
            h0[e] = 0.f; h1[e] = 0.f; h2[e] = 0.f; h3[e] = 0.f;
        }
        float p = 1.f;
        #pragma unroll
        for (int e = E - 1; e >= 0; --e) { Ks[e] = p; p *= alf[e]; }
    }

    // ---- one-time 'a' ladder (time-invariant scan coefficients) ----
    float saL[5];
    float sa = Ks[0] * alf[0];
    #pragma unroll
    for (int k = 0; k < 5; ++k) {
        saL[k] = sa;
        float ra = __shfl_up_sync(0xffffffffu, sa, 1 << k);
        if (lane >= (1 << k)) sa *= ra;
    }
    float eaC = __shfl_up_sync(0xffffffffu, sa, 1);
    if (lane == 0) eaC = 1.f;
    if (lane == 31) wtot[wid] = sa;
    __syncthreads();

    // cw[w2] = prod_{w3=w2+1}^{wid-1} wtot[w3] for w2 < wid, else 0.
    float cw[NWARPS - 1];
    {
        float p = 1.f;
        #pragma unroll
        for (int w3 = NWARPS - 2; w3 >= 0; --w3) {
            if (w3 < wid) { cw[w3] = p; p *= wtot[w3]; }
            else           cw[w3] = 0.f;
        }
    }
    __syncthreads();

    // =========================== main time loop ===========================
    #pragma unroll 2
    for (int t = 0; t < SEQ; ++t) {
        const float4 uv = *(const float4*)&xsv[SPB * t];
        const float cuK0 = (c_f * KT) * uv.x;
        const float cuK1 = (c_f * KT) * uv.y;
        const float cuK2 = (c_f * KT) * uv.z;
        const float cuK3 = (c_f * KT) * uv.w;

        // ---- thread-local: w_e and cb = sum Ks_e * w_e (all four streams) ----
        #pragma unroll
        for (int e = 0; e < E; ++e) {
            w0[e] = fmaf(gam[e], h0[e], dlt[e] * uv.x);
            w1[e] = fmaf(gam[e], h1[e], dlt[e] * uv.y);
            w2[e] = fmaf(gam[e], h2[e], dlt[e] * uv.z);
            w3[e] = fmaf(gam[e], h3[e], dlt[e] * uv.w);
        }
        float sb0 = 0.f, sb1 = 0.f, sb2 = 0.f, sb3 = 0.f;
        #pragma unroll
        for (int e = 0; e < E; ++e) {
            sb0 = fmaf(Ks[e], w0[e], sb0);
            sb1 = fmaf(Ks[e], w1[e], sb1);
            sb2 = fmaf(Ks[e], w2[e], sb2);
            sb3 = fmaf(Ks[e], w3[e], sb3);
        }

        // ---- warp inclusive scan on 'b', four independent streams ----
        #pragma unroll
        for (int k = 0; k < 5; ++k) {
            float rb0 = __shfl_up_sync(0xffffffffu, sb0, 1 << k);
            float rb1 = __shfl_up_sync(0xffffffffu, sb1, 1 << k);
            float rb2 = __shfl_up_sync(0xffffffffu, sb2, 1 << k);
            float rb3 = __shfl_up_sync(0xffffffffu, sb3, 1 << k);
            if (lane >= (1 << k)) {
                sb0 = fmaf(saL[k], rb0, sb0);
                sb1 = fmaf(saL[k], rb1, sb1);
                sb2 = fmaf(saL[k], rb2, sb2);
                sb3 = fmaf(saL[k], rb3, sb3);
            }
        }
        float eb0 = __shfl_up_sync(0xffffffffu, sb0, 1);
        float eb1 = __shfl_up_sync(0xffffffffu, sb1, 1);
        float eb2 = __shfl_up_sync(0xffffffffu, sb2, 1);
        float eb3 = __shfl_up_sync(0xffffffffu, sb3, 1);
        if (lane == 0) { eb0 = 0.f; eb1 = 0.f; eb2 = 0.f; eb3 = 0.f; }

        const int par = t & 1;                       // constant under unroll 2
        if (lane == 31) wtb[par][wid] = make_float4(sb0, sb1, sb2, sb3);
        __syncthreads();            // ONE barrier advances FOUR sequences one step

        // cross-warp: constant-weighted sums (no chain), LDS.128 per lower warp
        float gb0 = 0.f, gb1 = 0.f, gb2 = 0.f, gb3 = 0.f;
        #pragma unroll
        for (int w2 = 0; w2 < NWARPS - 1; ++w2) {
            if (w2 < wid) {
                const float4 v = wtb[par][w2];
                gb0 = fmaf(cw[w2], v.x, gb0);
                gb1 = fmaf(cw[w2], v.y, gb1);
                gb2 = fmaf(cw[w2], v.z, gb2);
                gb3 = fmaf(cw[w2], v.w, gb3);
            }
        }
        float r0 = fmaf(eaC, gb0, eb0);
        float r1 = fmaf(eaC, gb1, eb1);
        float r2 = fmaf(eaC, gb2, eb2);
        float r3 = fmaf(eaC, gb3, eb3);

        // ---- apply: four interleaved 1-FMA r-chains; paired-rcp tanh ----
        #pragma unroll
        for (int e = 0; e < E; ++e) {
            float rho0 = fmaf(mc2K, r0, cuK0);
            float rho1 = fmaf(mc2K, r1, cuK1);
            float rho2 = fmaf(mc2K, r2, cuK2);
            float rho3 = fmaf(mc2K, r3, cuK3);
            float xv0  = fmaf(gam[e], rho0, A1K[e] * h0[e]);
            float xv1  = fmaf(gam[e], rho1, A1K[e] * h1[e]);
            float xv2  = fmaf(gam[e], rho2, A1K[e] * h2[e]);
            float xv3  = fmaf(gam[e], rho3, A1K[e] * h3[e]);
            r0 = fmaf(alf[e], r0, w0[e]);
            r1 = fmaf(alf[e], r1, w1[e]);
            r2 = fmaf(alf[e], r2, w2[e]);
            r3 = fmaf(alf[e], r3, w3[e]);
            tanh_pair(xv0, xv1, h0[e], h1[e]);
            tanh_pair(xv2, xv3, h2[e], h3[e]);
        }
    }

    // ---- epilogue: y_s = C . h_s ; out[bidx*4+s][o] = y_s*W[o] + bias[o] ----
    float p0 = 0.f, p1 = 0.f, p2 = 0.f, p3 = 0.f;
    #pragma unroll
    for (int e = 0; e < E; ++e) {
        const float Ce = __ldg(&C[tid * E + e]);
        p0 = fmaf(Ce, h0[e], p0);
        p1 = fmaf(Ce, h1[e], p1);
        p2 = fmaf(Ce, h2[e], p2);
        p3 = fmaf(Ce, h3[e], p3);
    }
    #pragma unroll
    for (int d = 16; d > 0; d >>= 1) {
        p0 += __shfl_down_sync(0xffffffffu, p0, d);
        p1 += __shfl_down_sync(0xffffffffu, p1, d);
        p2 += __shfl_down_sync(0xffffffffu, p2, d);
        p3 += __shfl_down_sync(0xffffffffu, p3, d);
    }
    if (lane == 0) {
        red[wid][0] = p0; red[wid][1] = p1;
        red[wid][2] = p2; red[wid][3] = p3;
    }
    __syncthreads();
    if (tid < SPB) {
        float y = (red[0][tid] + red[1][tid]) + (red[2][tid] + red[3][tid]);
        #pragma unroll
        for (int o = 0; o < 10; ++o)
            out[(bidx * SPB + tid) * 10 + o] = fmaf(y, W[o], bias[o]);
    }
}

extern "C" void kernel_launch(void* const* d_in, const int* in_sizes, int n_in,
                              void* d_out, int out_size) {
    const float* x    = (const float*)d_in[0];   // (512, 784, 1)
    const float* C    = (const float*)d_in[1];   // (1, 1024)
    const float* W    = (const float*)d_in[2];   // (1, 10)
    const float* bias = (const float*)d_in[3];   // (10,)
    float* out        = (float*)d_out;           // (512, 10)
    ssm_scan_kernel<<<BATCH / SPB, NTHREADS>>>(x, C, W, bias, out);
}

// round 15
// speedup vs baseline: 1.2106x; 1.0776x over previous
#include <cuda_runtime.h>

#define HIDDEN   1024
#define SEQ      784
#define BATCH    512
#define NTHREADS 128
#define NWARPS   4
#define SPB      4                     // sequences per block, ALL carried by EVERY warp
#define E        8                     // hidden states per thread per sequence

typedef unsigned long long u64;

// ---- f32x2 packed helpers (sm_100+/sm_103a; FFMA2 reachable only via PTX) ----
__device__ __forceinline__ u64 pk(float lo, float hi) {
    u64 r; asm("mov.b64 %0, {%1, %2};" : "=l"(r) : "f"(lo), "f"(hi)); return r;
}
__device__ __forceinline__ void upk(u64 v, float& lo, float& hi) {
    asm("mov.b64 {%0, %1}, %2;" : "=f"(lo), "=f"(hi) : "l"(v));
}
__device__ __forceinline__ u64 fma2(u64 a, u64 b, u64 c) {
    u64 d; asm("fma.rn.f32x2 %0, %1, %2, %3;" : "=l"(d) : "l"(a), "l"(b), "l"(c)); return d;
}
__device__ __forceinline__ u64 mul2(u64 a, u64 b) {
    u64 d; asm("mul.rn.f32x2 %0, %1, %2;" : "=l"(d) : "l"(a), "l"(b)); return d;
}

// Quad tanh from pre-scaled args (xvK = (2/ln2)*xv), ONE rcp for 4 streams:
//   tanh = 1 - 2/d, d = 2^xvK + 1;  rc = rcp(d0 d1 d2 d3), unwound by muls.
// Clamp xvK <= 30 -> product <= ~2^120 never overflows; tanh(10.4) is within
// 3e-9 of 1 so the clamp is numerically invisible. MUFU: 4 ex2 + 1 rcp.
__device__ __forceinline__ void tanh_quad(float x0, float x1, float x2, float x3,
                                          float& t0, float& t1, float& t2, float& t3) {
    float e0, e1, e2, e3, rc;
    x0 = fminf(x0, 30.f); x1 = fminf(x1, 30.f);
    x2 = fminf(x2, 30.f); x3 = fminf(x3, 30.f);
    asm("ex2.approx.ftz.f32 %0, %1;" : "=f"(e0) : "f"(x0));
    asm("ex2.approx.ftz.f32 %0, %1;" : "=f"(e1) : "f"(x1));
    asm("ex2.approx.ftz.f32 %0, %1;" : "=f"(e2) : "f"(x2));
    asm("ex2.approx.ftz.f32 %0, %1;" : "=f"(e3) : "f"(x3));
    const float d0 = e0 + 1.f, d1 = e1 + 1.f, d2 = e2 + 1.f, d3 = e3 + 1.f;
    const float p01 = d0 * d1, p23 = d2 * d3;
    asm("rcp.approx.ftz.f32 %0, %1;" : "=f"(rc) : "f"(p01 * p23));
    const float rA = rc * p23, rB = rc * p01;   // 1/(d0 d1), 1/(d2 d3)
    t0 = fmaf(-2.f, rA * d1, 1.f);
    t1 = fmaf(-2.f, rA * d0, 1.f);
    t2 = fmaf(-2.f, rB * d3, 1.f);
    t3 = fmaf(-2.f, rB * d2, 1.f);
}

// One block serves FOUR batch sequences; every warp carries all four over the
// SAME hidden indices. Streams {0,1} and {2,3} are PACKED into f32x2 for all
// stream-parallel FMA work (w, sb, rho, xv, r-chain) -> FFMA2 halves issue
// count there. Ladder + tanh remain scalar (shfl/MUFU are 32-bit).
//
// HiPPO bilinear step collapses (A diagonal + rank-1 semiseparable) to ONE
// linear scan over hidden index i:
//   r_{i+1} = alf_i r_i + w_i,  w_i = gam_i h_i + dlt_i u      (r_0 = 0)
//   xv_i    = A1_i h_i + gam_i (c u - (c/2) r_i) ;  h_i = tanh(xv_i)
// Time-invariant multiplicative scan coefficients -> 'a' ladder (saL, eaC,
// cw) precomputed once; per step the warp scan runs on 'b' only.
__global__ void __launch_bounds__(NTHREADS, 1)
ssm_scan_kernel(const float* __restrict__ x,
                const float* __restrict__ C,
                const float* __restrict__ W,
                const float* __restrict__ bias,
                float* __restrict__ out)
{
    __shared__ float  xsv[SEQ * SPB];    // interleaved: xsv[4t+s] = u of seq s at step t
    __shared__ float4 wtb[2][NWARPS];    // warp totals (b) for 4 seqs, parity-buffered
    __shared__ float  wtot[NWARPS];
    __shared__ float  red[NWARPS][SPB];

    const int tid  = threadIdx.x;
    const int lane = tid & 31;
    const int wid  = tid >> 5;
    const int bidx = blockIdx.x;

    for (int i = tid; i < SPB * SEQ; i += NTHREADS) {
        const int s = i / SEQ, t = i - s * SEQ;
        xsv[SPB * t + s] = x[(bidx * SPB + s) * SEQ + t];
    }

    const float KT = 2.885390081777927f;          // 2/ln(2)

    // ---- per-element constants in double (matches reference fp64 HiPPO),
    //      stored PACKED (same value in both halves). ----
    u64 alf2[E], gam2[E], dlt2[E], A1K2[E];
    u64 h01[E], h23[E], w01[E], w23[E];
    float alf_s[E];                      // scalar copy for the 'a' ladder math
    u64 mc2K2;
    float cKT;
    {
        const double step = 1.0 / (double)SEQ;
        const double c    = 0.5 * step;
        cKT   = (float)c * KT;
        const float m = (float)(-0.5 * c) * KT;
        mc2K2 = pk(m, m);
        #pragma unroll
        for (int e = 0; e < E; ++e) {
            const double q = (double)(tid * E + e);
            const double P = sqrt(1.0 + 2.0 * q);
            const double D = 1.0 + c * (1.0 + q);
            const float a  = (float)((1.0 - c * q) / D);
            const float g  = (float)(2.0 * P / D);
            const float dl = (float)(step * P * P / D);
            const float a1 = (float)((1.0 - c * (1.0 + q)) / D) * KT;
            alf_s[e] = a;
            alf2[e] = pk(a, a); gam2[e] = pk(g, g);
            dlt2[e] = pk(dl, dl); A1K2[e] = pk(a1, a1);
            h01[e] = 0ull; h23[e] = 0ull;
        }
    }

    // ---- one-time 'a' ladder (time-invariant scan coefficients) ----
    float saL[5];
    float sa = 1.f;
    #pragma unroll
    for (int e = 0; e < E; ++e) sa *= alf_s[e];
    #pragma unroll
    for (int k = 0; k < 5; ++k) {
        saL[k] = sa;
        float ra = __shfl_up_sync(0xffffffffu, sa, 1 << k);
        if (lane >= (1 << k)) sa *= ra;
    }
    float eaC = __shfl_up_sync(0xffffffffu, sa, 1);
    if (lane == 0) eaC = 1.f;
    if (lane == 31) wtot[wid] = sa;
    __syncthreads();

    float cw[NWARPS - 1];
    {
        float p = 1.f;
        #pragma unroll
        for (int w3 = NWARPS - 2; w3 >= 0; --w3) {
            if (w3 < wid) { cw[w3] = p; p *= wtot[w3]; }
            else           cw[w3] = 0.f;
        }
    }
    __syncthreads();

    // =========================== main time loop ===========================
    #pragma unroll 2
    for (int t = 0; t < SEQ; ++t) {
        const float4 uv = *(const float4*)&xsv[SPB * t];
        const u64 u01 = pk(uv.x, uv.y), u23 = pk(uv.z, uv.w);
        const u64 cuK01 = pk(cKT * uv.x, cKT * uv.y);
        const u64 cuK23 = pk(cKT * uv.z, cKT * uv.w);

        // ---- thread-local: w_e (packed); sb via serial alf-weighted chain
        //      (same affine result as the Ks dot product, fewer registers). ----
        u64 sb01 = 0ull, sb23 = 0ull;
        #pragma unroll
        for (int e = 0; e < E; ++e) {
            w01[e] = fma2(gam2[e], h01[e], mul2(dlt2[e], u01));
            w23[e] = fma2(gam2[e], h23[e], mul2(dlt2[e], u23));
            sb01 = fma2(alf2[e], sb01, w01[e]);
            sb23 = fma2(alf2[e], sb23, w23[e]);
        }
        float sb0, sb1, sb2, sb3;
        upk(sb01, sb0, sb1); upk(sb23, sb2, sb3);

        // ---- warp inclusive scan on 'b', scalar, four independent streams ----
        #pragma unroll
        for (int k = 0; k < 5; ++k) {
            float rb0 = __shfl_up_sync(0xffffffffu, sb0, 1 << k);
            float rb1 = __shfl_up_sync(0xffffffffu, sb1, 1 << k);
            float rb2 = __shfl_up_sync(0xffffffffu, sb2, 1 << k);
            float rb3 = __shfl_up_sync(0xffffffffu, sb3, 1 << k);
            if (lane >= (1 << k)) {
                sb0 = fmaf(saL[k], rb0, sb0);
                sb1 = fmaf(saL[k], rb1, sb1);
                sb2 = fmaf(saL[k], rb2, sb2);
                sb3 = fmaf(saL[k], rb3, sb3);
            }
        }
        float eb0 = __shfl_up_sync(0xffffffffu, sb0, 1);
        float eb1 = __shfl_up_sync(0xffffffffu, sb1, 1);
        float eb2 = __shfl_up_sync(0xffffffffu, sb2, 1);
        float eb3 = __shfl_up_sync(0xffffffffu, sb3, 1);
        if (lane == 0) { eb0 = 0.f; eb1 = 0.f; eb2 = 0.f; eb3 = 0.f; }

        const int par = t & 1;
        if (lane == 31) wtb[par][wid] = make_float4(sb0, sb1, sb2, sb3);
        __syncthreads();            // ONE barrier advances FOUR sequences one step

        float gb0 = 0.f, gb1 = 0.f, gb2 = 0.f, gb3 = 0.f;
        #pragma unroll
        for (int w2 = 0; w2 < NWARPS - 1; ++w2) {
            if (w2 < wid) {
                const float4 v = wtb[par][w2];
                gb0 = fmaf(cw[w2], v.x, gb0);
                gb1 = fmaf(cw[w2], v.y, gb1);
                gb2 = fmaf(cw[w2], v.z, gb2);
                gb3 = fmaf(cw[w2], v.w, gb3);
            }
        }
        u64 r01 = pk(fmaf(eaC, gb0, eb0), fmaf(eaC, gb1, eb1));
        u64 r23 = pk(fmaf(eaC, gb2, eb2), fmaf(eaC, gb3, eb3));

        // ---- apply: packed 1-FMA r-chains; scalar quad-rcp tanh ----
        #pragma unroll
        for (int e = 0; e < E; ++e) {
            u64 rho01 = fma2(mc2K2, r01, cuK01);
            u64 rho23 = fma2(mc2K2, r23, cuK23);
            u64 xv01  = fma2(gam2[e], rho01, mul2(A1K2[e], h01[e]));
            u64 xv23  = fma2(gam2[e], rho23, mul2(A1K2[e], h23[e]));
            r01 = fma2(alf2[e], r01, w01[e]);
            r23 = fma2(alf2[e], r23, w23[e]);
            float x0, x1, x2, x3, t0, t1, t2, t3;
            upk(xv01, x0, x1); upk(xv23, x2, x3);
            tanh_quad(x0, x1, x2, x3, t0, t1, t2, t3);
            h01[e] = pk(t0, t1);
            h23[e] = pk(t2, t3);
        }
    }

    // ---- epilogue: y_s = C . h_s ; out[bidx*4+s][o] = y_s*W[o] + bias[o] ----
    float p0 = 0.f, p1 = 0.f, p2 = 0.f, p3 = 0.f;
    #pragma unroll
    for (int e = 0; e < E; ++e) {
        const float Ce = __ldg(&C[tid * E + e]);
        float a, b;
        upk(h01[e], a, b); p0 = fmaf(Ce, a, p0); p1 = fmaf(Ce, b, p1);
        upk(h23[e], a, b); p2 = fmaf(Ce, a, p2); p3 = fmaf(Ce, b, p3);
    }
    #pragma unroll
    for (int d = 16; d > 0; d >>= 1) {
        p0 += __shfl_down_sync(0xffffffffu, p0, d);
        p1 += __shfl_down_sync(0xffffffffu, p1, d);
        p2 += __shfl_down_sync(0xffffffffu, p2, d);
        p3 += __shfl_down_sync(0xffffffffu, p3, d);
    }
    if (lane == 0) {
        red[wid][0] = p0; red[wid][1] = p1;
        red[wid][2] = p2; red[wid][3] = p3;
    }
    __syncthreads();
    if (tid < SPB) {
        float y = (red[0][tid] + red[1][tid]) + (red[2][tid] + red[3][tid]);
        #pragma unroll
        for (int o = 0; o < 10; ++o)
            out[(bidx * SPB + tid) * 10 + o] = fmaf(y, W[o], bias[o]);
    }
}

extern "C" void kernel_launch(void* const* d_in, const int* in_sizes, int n_in,
                              void* d_out, int out_size) {
    const float* x    = (const float*)d_in[0];   // (512, 784, 1)
    const float* C    = (const float*)d_in[1];   // (1, 1024)
    const float* W    = (const float*)d_in[2];   // (1, 10)
    const float* bias = (const float*)d_in[3];   // (10,)
    float* out        = (float*)d_out;           // (512, 10)
    ssm_scan_kernel<<<BATCH / SPB, NTHREADS>>>(x, C, W, bias, out);
}